// round 10
// baseline (speedup 1.0000x reference)
#include <cuda_runtime.h>

// 5x5 box-filter mean, reflect padding, NCHW fp32, H=W=512.
// smem-free, vertical-first tree partials + shuffle horizontal.
// R10: 2 output rows / 6 input rows per thread (was 4/8) -> ~48 regs,
// 5 CTAs/SM, more warps in flight to hide DRAM latency. Halo loads deferred
// (L1 hits); interior-y fast path with immediate offsets.

#define IMG 512
#define TW  128   // tile width  (floats) = 32 lanes * 4
#define TH  16    // tile height (rows)   = 8 warps * 2

__device__ __forceinline__ int refl(int x) {
    return (x < 0) ? -x : ((x >= IMG) ? (2 * IMG - 2 - x) : x);
}

__global__ __launch_bounds__(256, 5)
void box5_kernel(const float* __restrict__ in, float* __restrict__ out)
{
    const int lane = threadIdx.x;       // 0..31 -> float4 column
    const int wrp  = threadIdx.y;       // 0..7  -> 2-row group

    const int tile_x = blockIdx.x * TW;
    const int tile_y = blockIdx.y * TH;
    const float* __restrict__ img  = in  + (size_t)blockIdx.z * (IMG * IMG);
    float* __restrict__       oimg = out + (size_t)blockIdx.z * (IMG * IMG);

    const int colx  = tile_x + lane * 4;
    const int rbase = tile_y + wrp * 2 - 2;   // first of 6 input rows

    const bool interior_y = (rbase >= 0) && (rbase + 5 < IMG);

    // ---- Front-batched loads: 6 rows x LDG.128 ----
    float4 c[6];
    if (interior_y) {
        const float* p = img + rbase * IMG + colx;
        #pragma unroll
        for (int k = 0; k < 6; k++)
            c[k] = *reinterpret_cast<const float4*>(p + k * IMG);  // imm offsets
    } else {
        #pragma unroll
        for (int k = 0; k < 6; k++)
            c[k] = *reinterpret_cast<const float4*>(img + refl(rbase + k) * IMG + colx);
    }

    // ---- Vertical 5-sums via tree partials (c[] dies here) ----
    //   m = (c1+c2)+(c3+c4) ; v0 = c0+m ; v1 = m+c5
    float4 m, v[2];
    m.x = (c[1].x + c[2].x) + (c[3].x + c[4].x);
    m.y = (c[1].y + c[2].y) + (c[3].y + c[4].y);
    m.z = (c[1].z + c[2].z) + (c[3].z + c[4].z);
    m.w = (c[1].w + c[2].w) + (c[3].w + c[4].w);
    v[0].x = c[0].x + m.x;  v[0].y = c[0].y + m.y;
    v[0].z = c[0].z + m.z;  v[0].w = c[0].w + m.w;
    v[1].x = m.x + c[5].x;  v[1].y = m.y + c[5].y;
    v[1].z = m.z + c[5].z;  v[1].w = m.w + c[5].w;

    // ---- Deferred x-halo (L1 hits) for lanes 0/31, tree-summed ----
    float2 ve[2] = {};
    if (lane == 0 || lane == 31) {
        const bool left = (lane == 0);
        float2 e[6];
        if (left) {
            if (tile_x == 0) {
                #pragma unroll
                for (int k = 0; k < 6; k++) {          // reflect: -2 -> 2, -1 -> 1
                    const float* rp = img + refl(rbase + k) * IMG;
                    e[k].x = rp[2];
                    e[k].y = rp[1];
                }
            } else {
                #pragma unroll
                for (int k = 0; k < 6; k++)            // even offset -> aligned LDG.64
                    e[k] = *reinterpret_cast<const float2*>(
                        img + refl(rbase + k) * IMG + tile_x - 2);
            }
        } else {
            if (tile_x + TW == IMG) {
                #pragma unroll
                for (int k = 0; k < 6; k++) {          // reflect: 512 -> 510, 513 -> 509
                    const float* rp = img + refl(rbase + k) * IMG;
                    e[k].x = rp[IMG - 2];
                    e[k].y = rp[IMG - 3];
                }
            } else {
                #pragma unroll
                for (int k = 0; k < 6; k++)            // even offset -> aligned LDG.64
                    e[k] = *reinterpret_cast<const float2*>(
                        img + refl(rbase + k) * IMG + tile_x + TW);
            }
        }
        float2 em;
        em.x = (e[1].x + e[2].x) + (e[3].x + e[4].x);
        em.y = (e[1].y + e[2].y) + (e[3].y + e[4].y);
        ve[0].x = e[0].x + em.x;  ve[0].y = e[0].y + em.y;
        ve[1].x = em.x + e[5].x;  ve[1].y = em.y + e[5].y;
    }

    // ---- Horizontal 5-tap on summed rows (4 shuffles/row) + store ----
    const float inv25 = 1.0f / 25.0f;
    float* obase = oimg + (tile_y + wrp * 2) * IMG + colx;

    #pragma unroll
    for (int r = 0; r < 2; r++) {
        float pz = __shfl_up_sync(0xffffffffu, v[r].z, 1);   // col -2
        float pw = __shfl_up_sync(0xffffffffu, v[r].w, 1);   // col -1
        float nx = __shfl_down_sync(0xffffffffu, v[r].x, 1); // col +4
        float ny = __shfl_down_sync(0xffffffffu, v[r].y, 1); // col +5
        if (lane == 0)  { pz = ve[r].x; pw = ve[r].y; }
        if (lane == 31) { nx = ve[r].x; ny = ve[r].y; }

        const float s = v[r].x + v[r].y + v[r].z + v[r].w;
        float4 o;
        o.x = ((s - v[r].w) + pz + pw) * inv25;   // cols -2..2
        o.y = (s + pw) * inv25;                   // cols -1..3
        o.z = (s + nx) * inv25;                   // cols  0..4
        o.w = ((s - v[r].x) + nx + ny) * inv25;   // cols  1..5
        *reinterpret_cast<float4*>(obase + r * IMG) = o;
    }
}

extern "C" void kernel_launch(void* const* d_in, const int* in_sizes, int n_in,
                              void* d_out, int out_size)
{
    const float* in = (const float*)d_in[0];
    float* out = (float*)d_out;

    const int planes = in_sizes[0] / (IMG * IMG);   // 96

    dim3 grid(IMG / TW, IMG / TH, planes);          // (4, 32, 96)
    dim3 block(32, 8);
    box5_kernel<<<grid, block>>>(in, out);
}

// round 11
// speedup vs baseline: 1.1730x; 1.1730x over previous
#include <cuda_runtime.h>

// 5x5 box-filter mean, reflect padding, NCHW fp32, H=W=512.
// R11 = R9 per-thread code exactly (4 output rows / 8 input rows, vertical
// tree partials, deferred halo, shuffle horizontal) with 128-thread CTAs:
// 7168 regs/CTA -> 9 CTAs/SM (36 warps) vs 4x256-thr (28 warps). Single
// variable: occupancy via allocation granularity.

#define IMG 512
#define TW  128   // tile width  (floats) = 32 lanes * 4
#define TH  16    // tile height (rows)   = 4 warps * 4

__device__ __forceinline__ int refl(int x) {
    return (x < 0) ? -x : ((x >= IMG) ? (2 * IMG - 2 - x) : x);
}

__global__ __launch_bounds__(128, 8)
void box5_kernel(const float* __restrict__ in, float* __restrict__ out)
{
    const int lane = threadIdx.x;       // 0..31 -> float4 column
    const int wrp  = threadIdx.y;       // 0..3  -> 4-row group

    const int tile_x = blockIdx.x * TW;
    const int tile_y = blockIdx.y * TH;
    const float* __restrict__ img  = in  + (size_t)blockIdx.z * (IMG * IMG);
    float* __restrict__       oimg = out + (size_t)blockIdx.z * (IMG * IMG);

    const int colx  = tile_x + lane * 4;
    const int rbase = tile_y + wrp * 4 - 2;   // first of 8 input rows

    const bool interior_y = (rbase >= 0) && (rbase + 7 < IMG);

    // ---- Front-batched loads: 8 rows x LDG.128 ----
    float4 c[8];
    if (interior_y) {
        const float* p = img + rbase * IMG + colx;
        #pragma unroll
        for (int k = 0; k < 8; k++)
            c[k] = *reinterpret_cast<const float4*>(p + k * IMG);  // imm offsets
    } else {
        #pragma unroll
        for (int k = 0; k < 8; k++)
            c[k] = *reinterpret_cast<const float4*>(img + refl(rbase + k) * IMG + colx);
    }

    // ---- Vertical 5-sums via tree partials (c[] dies here) ----
    //   a = c1+c2, b = c3+c4, d = c5+c6
    //   v0 = c0+a+b ; v1 = a+b+c5 ; v2 = c2+b+d ; v3 = b+d+c7
    float4 a, b, d;
    a.x = c[1].x + c[2].x;  a.y = c[1].y + c[2].y;  a.z = c[1].z + c[2].z;  a.w = c[1].w + c[2].w;
    b.x = c[3].x + c[4].x;  b.y = c[3].y + c[4].y;  b.z = c[3].z + c[4].z;  b.w = c[3].w + c[4].w;
    d.x = c[5].x + c[6].x;  d.y = c[5].y + c[6].y;  d.z = c[5].z + c[6].z;  d.w = c[5].w + c[6].w;

    float4 v[4];
    v[0].x = c[0].x + a.x + b.x;  v[0].y = c[0].y + a.y + b.y;
    v[0].z = c[0].z + a.z + b.z;  v[0].w = c[0].w + a.w + b.w;
    v[1].x = a.x + b.x + c[5].x;  v[1].y = a.y + b.y + c[5].y;
    v[1].z = a.z + b.z + c[5].z;  v[1].w = a.w + b.w + c[5].w;
    v[2].x = c[2].x + b.x + d.x;  v[2].y = c[2].y + b.y + d.y;
    v[2].z = c[2].z + b.z + d.z;  v[2].w = c[2].w + b.w + d.w;
    v[3].x = b.x + d.x + c[7].x;  v[3].y = b.y + d.y + c[7].y;
    v[3].z = b.z + d.z + c[7].z;  v[3].w = b.w + d.w + c[7].w;

    // ---- Deferred x-halo (L1 hits) for lanes 0/31, then vertical tree ----
    float2 ve[4] = {};
    if (lane == 0 || lane == 31) {
        const bool left = (lane == 0);
        float2 e[8];
        if (left) {
            if (tile_x == 0) {
                #pragma unroll
                for (int k = 0; k < 8; k++) {          // reflect: -2 -> 2, -1 -> 1
                    const float* rp = img + refl(rbase + k) * IMG;
                    e[k].x = rp[2];
                    e[k].y = rp[1];
                }
            } else {
                #pragma unroll
                for (int k = 0; k < 8; k++)            // even offset -> aligned LDG.64
                    e[k] = *reinterpret_cast<const float2*>(
                        img + refl(rbase + k) * IMG + tile_x - 2);
            }
        } else {
            if (tile_x + TW == IMG) {
                #pragma unroll
                for (int k = 0; k < 8; k++) {          // reflect: 512 -> 510, 513 -> 509
                    const float* rp = img + refl(rbase + k) * IMG;
                    e[k].x = rp[IMG - 2];
                    e[k].y = rp[IMG - 3];
                }
            } else {
                #pragma unroll
                for (int k = 0; k < 8; k++)            // even offset -> aligned LDG.64
                    e[k] = *reinterpret_cast<const float2*>(
                        img + refl(rbase + k) * IMG + tile_x + TW);
            }
        }
        float2 ae, be, de;
        ae.x = e[1].x + e[2].x;  ae.y = e[1].y + e[2].y;
        be.x = e[3].x + e[4].x;  be.y = e[3].y + e[4].y;
        de.x = e[5].x + e[6].x;  de.y = e[5].y + e[6].y;
        ve[0].x = e[0].x + ae.x + be.x;  ve[0].y = e[0].y + ae.y + be.y;
        ve[1].x = ae.x + be.x + e[5].x;  ve[1].y = ae.y + be.y + e[5].y;
        ve[2].x = e[2].x + be.x + de.x;  ve[2].y = e[2].y + be.y + de.y;
        ve[3].x = be.x + de.x + e[7].x;  ve[3].y = be.y + de.y + e[7].y;
    }

    // ---- Horizontal 5-tap on summed rows (4 shuffles/row) + store ----
    const float inv25 = 1.0f / 25.0f;
    float* obase = oimg + (tile_y + wrp * 4) * IMG + colx;

    #pragma unroll
    for (int r = 0; r < 4; r++) {
        float pz = __shfl_up_sync(0xffffffffu, v[r].z, 1);   // col -2
        float pw = __shfl_up_sync(0xffffffffu, v[r].w, 1);   // col -1
        float nx = __shfl_down_sync(0xffffffffu, v[r].x, 1); // col +4
        float ny = __shfl_down_sync(0xffffffffu, v[r].y, 1); // col +5
        if (lane == 0)  { pz = ve[r].x; pw = ve[r].y; }
        if (lane == 31) { nx = ve[r].x; ny = ve[r].y; }

        const float s = v[r].x + v[r].y + v[r].z + v[r].w;
        float4 o;
        o.x = ((s - v[r].w) + pz + pw) * inv25;   // cols -2..2
        o.y = (s + pw) * inv25;                   // cols -1..3
        o.z = (s + nx) * inv25;                   // cols  0..4
        o.w = ((s - v[r].x) + nx + ny) * inv25;   // cols  1..5
        *reinterpret_cast<float4*>(obase + r * IMG) = o;
    }
}

extern "C" void kernel_launch(void* const* d_in, const int* in_sizes, int n_in,
                              void* d_out, int out_size)
{
    const float* in = (const float*)d_in[0];
    float* out = (float*)d_out;

    const int planes = in_sizes[0] / (IMG * IMG);   // 96

    dim3 grid(IMG / TW, IMG / TH, planes);          // (4, 32, 96)
    dim3 block(32, 4);
    box5_kernel<<<grid, block>>>(in, out);
}

// round 12
// speedup vs baseline: 1.1741x; 1.0009x over previous
#include <cuda_runtime.h>

// 5x5 box-filter mean, reflect padding, NCHW fp32, H=W=512.
// R12 = R11 (128-thr CTAs, 4 out rows / 8 in rows per thread, vertical tree
// partials, deferred halo, shuffle horizontal) plus:
//   - __stcs streaming stores (output is write-once: keep it out of L2 so
//     input halo re-reads stay resident)
//   - interior-y fast path for the halo loads too (fewer IMADs)
//   - __launch_bounds__(128, 9): full 9-CTA/SM residency at 56 regs

#define IMG 512
#define TW  128   // tile width  (floats) = 32 lanes * 4
#define TH  16    // tile height (rows)   = 4 warps * 4

__device__ __forceinline__ int refl(int x) {
    return (x < 0) ? -x : ((x >= IMG) ? (2 * IMG - 2 - x) : x);
}

__global__ __launch_bounds__(128, 9)
void box5_kernel(const float* __restrict__ in, float* __restrict__ out)
{
    const int lane = threadIdx.x;       // 0..31 -> float4 column
    const int wrp  = threadIdx.y;       // 0..3  -> 4-row group

    const int tile_x = blockIdx.x * TW;
    const int tile_y = blockIdx.y * TH;
    const float* __restrict__ img  = in  + (size_t)blockIdx.z * (IMG * IMG);
    float* __restrict__       oimg = out + (size_t)blockIdx.z * (IMG * IMG);

    const int colx  = tile_x + lane * 4;
    const int rbase = tile_y + wrp * 4 - 2;   // first of 8 input rows

    const bool interior_y = (rbase >= 0) && (rbase + 7 < IMG);

    // ---- Front-batched loads: 8 rows x LDG.128 ----
    float4 c[8];
    if (interior_y) {
        const float* p = img + rbase * IMG + colx;
        #pragma unroll
        for (int k = 0; k < 8; k++)
            c[k] = *reinterpret_cast<const float4*>(p + k * IMG);  // imm offsets
    } else {
        #pragma unroll
        for (int k = 0; k < 8; k++)
            c[k] = *reinterpret_cast<const float4*>(img + refl(rbase + k) * IMG + colx);
    }

    // ---- Vertical 5-sums via tree partials (c[] dies here) ----
    //   a = c1+c2, b = c3+c4, d = c5+c6
    //   v0 = c0+a+b ; v1 = a+b+c5 ; v2 = c2+b+d ; v3 = b+d+c7
    float4 a, b, d;
    a.x = c[1].x + c[2].x;  a.y = c[1].y + c[2].y;  a.z = c[1].z + c[2].z;  a.w = c[1].w + c[2].w;
    b.x = c[3].x + c[4].x;  b.y = c[3].y + c[4].y;  b.z = c[3].z + c[4].z;  b.w = c[3].w + c[4].w;
    d.x = c[5].x + c[6].x;  d.y = c[5].y + c[6].y;  d.z = c[5].z + c[6].z;  d.w = c[5].w + c[6].w;

    float4 v[4];
    v[0].x = c[0].x + a.x + b.x;  v[0].y = c[0].y + a.y + b.y;
    v[0].z = c[0].z + a.z + b.z;  v[0].w = c[0].w + a.w + b.w;
    v[1].x = a.x + b.x + c[5].x;  v[1].y = a.y + b.y + c[5].y;
    v[1].z = a.z + b.z + c[5].z;  v[1].w = a.w + b.w + c[5].w;
    v[2].x = c[2].x + b.x + d.x;  v[2].y = c[2].y + b.y + d.y;
    v[2].z = c[2].z + b.z + d.z;  v[2].w = c[2].w + b.w + d.w;
    v[3].x = b.x + d.x + c[7].x;  v[3].y = b.y + d.y + c[7].y;
    v[3].z = b.z + d.z + c[7].z;  v[3].w = b.w + d.w + c[7].w;

    // ---- Deferred x-halo (L1 hits) for lanes 0/31, then vertical tree ----
    float2 ve[4] = {};
    if (lane == 0 || lane == 31) {
        const bool left = (lane == 0);
        float2 e[8];
        if (left) {
            if (tile_x == 0) {
                #pragma unroll
                for (int k = 0; k < 8; k++) {          // reflect: -2 -> 2, -1 -> 1
                    const float* rp = img + refl(rbase + k) * IMG;
                    e[k].x = rp[2];
                    e[k].y = rp[1];
                }
            } else if (interior_y) {
                const float* p = img + rbase * IMG + tile_x - 2;
                #pragma unroll
                for (int k = 0; k < 8; k++)
                    e[k] = *reinterpret_cast<const float2*>(p + k * IMG);
            } else {
                #pragma unroll
                for (int k = 0; k < 8; k++)
                    e[k] = *reinterpret_cast<const float2*>(
                        img + refl(rbase + k) * IMG + tile_x - 2);
            }
        } else {
            if (tile_x + TW == IMG) {
                #pragma unroll
                for (int k = 0; k < 8; k++) {          // reflect: 512 -> 510, 513 -> 509
                    const float* rp = img + refl(rbase + k) * IMG;
                    e[k].x = rp[IMG - 2];
                    e[k].y = rp[IMG - 3];
                }
            } else if (interior_y) {
                const float* p = img + rbase * IMG + tile_x + TW;
                #pragma unroll
                for (int k = 0; k < 8; k++)
                    e[k] = *reinterpret_cast<const float2*>(p + k * IMG);
            } else {
                #pragma unroll
                for (int k = 0; k < 8; k++)
                    e[k] = *reinterpret_cast<const float2*>(
                        img + refl(rbase + k) * IMG + tile_x + TW);
            }
        }
        float2 ae, be, de;
        ae.x = e[1].x + e[2].x;  ae.y = e[1].y + e[2].y;
        be.x = e[3].x + e[4].x;  be.y = e[3].y + e[4].y;
        de.x = e[5].x + e[6].x;  de.y = e[5].y + e[6].y;
        ve[0].x = e[0].x + ae.x + be.x;  ve[0].y = e[0].y + ae.y + be.y;
        ve[1].x = ae.x + be.x + e[5].x;  ve[1].y = ae.y + be.y + e[5].y;
        ve[2].x = e[2].x + be.x + de.x;  ve[2].y = e[2].y + be.y + de.y;
        ve[3].x = be.x + de.x + e[7].x;  ve[3].y = be.y + de.y + e[7].y;
    }

    // ---- Horizontal 5-tap on summed rows (4 shuffles/row) + streaming store ----
    const float inv25 = 1.0f / 25.0f;
    float* obase = oimg + (tile_y + wrp * 4) * IMG + colx;

    #pragma unroll
    for (int r = 0; r < 4; r++) {
        float pz = __shfl_up_sync(0xffffffffu, v[r].z, 1);   // col -2
        float pw = __shfl_up_sync(0xffffffffu, v[r].w, 1);   // col -1
        float nx = __shfl_down_sync(0xffffffffu, v[r].x, 1); // col +4
        float ny = __shfl_down_sync(0xffffffffu, v[r].y, 1); // col +5
        if (lane == 0)  { pz = ve[r].x; pw = ve[r].y; }
        if (lane == 31) { nx = ve[r].x; ny = ve[r].y; }

        const float s = v[r].x + v[r].y + v[r].z + v[r].w;
        float4 o;
        o.x = ((s - v[r].w) + pz + pw) * inv25;   // cols -2..2
        o.y = (s + pw) * inv25;                   // cols -1..3
        o.z = (s + nx) * inv25;                   // cols  0..4
        o.w = ((s - v[r].x) + nx + ny) * inv25;   // cols  1..5
        __stcs(reinterpret_cast<float4*>(obase + r * IMG), o);
    }
}

extern "C" void kernel_launch(void* const* d_in, const int* in_sizes, int n_in,
                              void* d_out, int out_size)
{
    const float* in = (const float*)d_in[0];
    float* out = (float*)d_out;

    const int planes = in_sizes[0] / (IMG * IMG);   // 96

    dim3 grid(IMG / TW, IMG / TH, planes);          // (4, 32, 96)
    dim3 block(32, 4);
    box5_kernel<<<grid, block>>>(in, out);
}